// round 16
// baseline (speedup 1.0000x reference)
#include <cuda_runtime.h>
#include <cuda_fp16.h>
#include <mma.h>
#include <cstdint>
#include <cstddef>

using namespace nvcuda;

#define BB 2
#define SS 2048
#define DD 512
#define HH 8
#define HDIM 64
#define KROUTE 64

// ---------------------------------------------------------------------------
// Scratch (device globals; no allocation allowed)
// ---------------------------------------------------------------------------
__device__ float g_q[BB * HH * SS * HDIM];
__device__ __align__(16) __half gk[BB * HH * SS * HDIM];
__device__ __align__(16) __half gv[BB * HH * SS * HDIM];

__device__ __align__(16) __half gx[BB * SS * DD];
__device__ __align__(16) __half gw1[DD * 3 * DD];
__device__ __align__(16) __half gw2[DD * DD];
__device__ __align__(16) __half gat[BB * SS * DD];

// ---------------------------------------------------------------------------
__device__ __forceinline__ void cp16(void* d, const void* s)
{
    unsigned ds = (unsigned)__cvta_generic_to_shared(d);
    asm volatile("cp.async.cg.shared.global [%0], [%1], 16;" :: "r"(ds), "l"(s));
}

// ---------------------------------------------------------------------------
// Fused fp32 -> fp16 conversion for x, Wqkv, Wout (single launch)
// ---------------------------------------------------------------------------
#define N4_X  ((BB * SS * DD) / 4)
#define N4_W1 ((DD * 3 * DD) / 4)
#define N4_W2 ((DD * DD) / 4)

__global__ __launch_bounds__(256) void cvt_all(
    const float4* __restrict__ x, const float4* __restrict__ w1,
    const float4* __restrict__ w2)
{
    int i = blockIdx.x * 256 + threadIdx.x;
    const float4* src;
    __half2* dst;
    if (i < N4_X) {
        src = x + i;
        dst = (__half2*)gx + 2 * i;
    } else if (i < N4_X + N4_W1) {
        const int j = i - N4_X;
        src = w1 + j;
        dst = (__half2*)gw1 + 2 * j;
    } else if (i < N4_X + N4_W1 + N4_W2) {
        const int j = i - N4_X - N4_W1;
        src = w2 + j;
        dst = (__half2*)gw2 + 2 * j;
    } else {
        return;
    }
    const float4 v = *src;
    dst[0] = __floats2half2_rn(v.x, v.y);
    dst[1] = __floats2half2_rn(v.z, v.w);
}

// ---------------------------------------------------------------------------
// Tensor-core GEMM (QKV), fp16 x fp16 -> fp32. 128x128x32 tile, 2-stage
// cp.async, 2 CTAs/SM. 8 warps: 4(m) x 2(n).
// Scatter epilogue: q->fp32, k/v->fp16 (head reshuffle), half2/float2 stores.
// ---------------------------------------------------------------------------
__global__ __launch_bounds__(256, 2) void gemm_qkv(
    const __half* __restrict__ A, const __half* __restrict__ B,
    const float* __restrict__ bias, int M, int N, int Kd)
{
    extern __shared__ __align__(16) char smem[];
    constexpr int BM = 128, BN = 128, BK = 32;
    constexpr int LDA = BK + 8;
    constexpr int LDB = BN + 8;
    constexpr int LDS_ = BN + 4;
    constexpr int A_SZ = BM * LDA;
    constexpr int B_SZ = BK * LDB;
    constexpr int STG = A_SZ + B_SZ;

    __half* base = (__half*)smem;
    float* stagef = (float*)smem;

    const int tid = threadIdx.x;
    const int wid = tid >> 5;
    const int wm = wid & 3;
    const int wn = wid >> 2;

    const size_t aBase = (size_t)blockIdx.y * BM * Kd;
    const int nBase = blockIdx.x * BN;
    const int nK = Kd / BK;

    wmma::fragment<wmma::accumulator, 16, 16, 16, float> acc[2][4];
    #pragma unroll
    for (int mi = 0; mi < 2; mi++)
        #pragma unroll
        for (int ni = 0; ni < 4; ni++) wmma::fill_fragment(acc[mi][ni], 0.0f);

    auto prefetch = [&](int ks, int st) {
        const int k0 = ks * BK;
        __half* sA = base + st * STG;
        __half* sB = sA + A_SZ;
        #pragma unroll
        for (int i = 0; i < 2; i++) {
            const int c = tid + 256 * i;
            const int rA = c >> 2, cA = (c & 3) * 8;
            cp16(&sA[rA * LDA + cA], A + aBase + (size_t)rA * Kd + k0 + cA);
            const int rB = c >> 4, cB = (c & 15) * 8;
            cp16(&sB[rB * LDB + cB], B + (size_t)(k0 + rB) * N + nBase + cB);
        }
        asm volatile("cp.async.commit_group;");
    };

    prefetch(0, 0);

    for (int ks = 0; ks < nK; ks++) {
        if (ks + 1 < nK) {
            prefetch(ks + 1, (ks + 1) & 1);
            asm volatile("cp.async.wait_group 1;");
        } else {
            asm volatile("cp.async.wait_group 0;");
        }
        __syncthreads();

        const int st = ks & 1;
        const __half* sA = base + st * STG;
        const __half* sB = sA + A_SZ;

        #pragma unroll
        for (int kk = 0; kk < BK; kk += 16) {
            wmma::fragment<wmma::matrix_a, 16, 16, 16, __half, wmma::row_major> a[2];
            #pragma unroll
            for (int mi = 0; mi < 2; mi++)
                wmma::load_matrix_sync(a[mi], sA + (wm * 32 + mi * 16) * LDA + kk, LDA);
            #pragma unroll
            for (int ni = 0; ni < 4; ni++) {
                wmma::fragment<wmma::matrix_b, 16, 16, 16, __half, wmma::row_major> b;
                wmma::load_matrix_sync(b, sB + kk * LDB + wn * 64 + ni * 16, LDB);
                #pragma unroll
                for (int mi = 0; mi < 2; mi++)
                    wmma::mma_sync(acc[mi][ni], a[mi], b, acc[mi][ni]);
            }
        }
        __syncthreads();
    }

    #pragma unroll
    for (int half = 0; half < 2; half++) {
        if ((wm >> 1) == half) {
            #pragma unroll
            for (int mi = 0; mi < 2; mi++)
                #pragma unroll
                for (int ni = 0; ni < 4; ni++)
                    wmma::store_matrix_sync(
                        stagef + ((wm & 1) * 32 + mi * 16) * LDS_ + wn * 64 + ni * 16,
                        acc[mi][ni], LDS_, wmma::mem_row_major);
        }
        __syncthreads();
        #pragma unroll 4
        for (int i = 0; i < (64 * BN) / (256 * 2); i++) {
            const int flat = i * 256 + tid;
            const int r = flat >> 6;
            const int c2 = flat & 63;
            const int n = nBase + c2 * 2;
            const float v0 = stagef[r * LDS_ + c2 * 2 + 0] + __ldg(&bias[n + 0]);
            const float v1 = stagef[r * LDS_ + c2 * 2 + 1] + __ldg(&bias[n + 1]);
            const int m = blockIdx.y * BM + half * 64 + r;
            const int b = m >> 11;
            const int s = m & 2047;
            const int c3 = n >> 9;
            const int h = (n >> 6) & 7;
            const int d = n & 63;
            const size_t off = (((size_t)b * HH + h) * SS + s) * HDIM + d;
            if (c3 == 0)      *(float2*)&g_q[off] = make_float2(v0, v1);
            else if (c3 == 1) *(__half2*)&gk[off] = __floats2half2_rn(v0, v1);
            else              *(__half2*)&gv[off] = __floats2half2_rn(v0, v1);
        }
        __syncthreads();
    }
}

// ---------------------------------------------------------------------------
// Out-projection GEMM: 64x128x32 tile (grid 4x64 = 256 CTAs), 2-stage
// cp.async, 3 CTAs/SM. 8 warps: 2(m) x 4(n), 32x32 warp tile.
// ---------------------------------------------------------------------------
__global__ __launch_bounds__(256, 3) void gemm_out(
    const __half* __restrict__ A, const __half* __restrict__ B,
    const float* __restrict__ bias, float* __restrict__ C,
    int M, int N, int Kd)
{
    extern __shared__ __align__(16) char smem[];
    constexpr int BM = 64, BN = 128, BK = 32;
    constexpr int LDA = BK + 8;    // 40
    constexpr int LDB = BN + 8;    // 136
    constexpr int LDS_ = BN + 4;   // 132
    constexpr int A_SZ = BM * LDA; // 2560
    constexpr int B_SZ = BK * LDB; // 4352
    constexpr int STG = A_SZ + B_SZ;

    __half* base = (__half*)smem;
    float* stagef = (float*)smem;

    const int tid = threadIdx.x;
    const int wid = tid >> 5;
    const int wm = wid & 1;
    const int wn = wid >> 1;

    const size_t aBase = (size_t)blockIdx.y * BM * Kd;
    const int nBase = blockIdx.x * BN;
    const int nK = Kd / BK;

    wmma::fragment<wmma::accumulator, 16, 16, 16, float> acc[2][2];
    #pragma unroll
    for (int mi = 0; mi < 2; mi++)
        #pragma unroll
        for (int ni = 0; ni < 2; ni++) wmma::fill_fragment(acc[mi][ni], 0.0f);

    auto prefetch = [&](int ks, int st) {
        const int k0 = ks * BK;
        __half* sA = base + st * STG;
        __half* sB = sA + A_SZ;
        {
            const int rA = tid >> 2, cA = (tid & 3) * 8;
            cp16(&sA[rA * LDA + cA], A + aBase + (size_t)rA * Kd + k0 + cA);
        }
        #pragma unroll
        for (int i = 0; i < 2; i++) {
            const int c = tid + 256 * i;
            const int rB = c >> 4, cB = (c & 15) * 8;
            cp16(&sB[rB * LDB + cB], B + (size_t)(k0 + rB) * N + nBase + cB);
        }
        asm volatile("cp.async.commit_group;");
    };

    prefetch(0, 0);

    for (int ks = 0; ks < nK; ks++) {
        if (ks + 1 < nK) {
            prefetch(ks + 1, (ks + 1) & 1);
            asm volatile("cp.async.wait_group 1;");
        } else {
            asm volatile("cp.async.wait_group 0;");
        }
        __syncthreads();

        const int st = ks & 1;
        const __half* sA = base + st * STG;
        const __half* sB = sA + A_SZ;

        #pragma unroll
        for (int kk = 0; kk < BK; kk += 16) {
            wmma::fragment<wmma::matrix_a, 16, 16, 16, __half, wmma::row_major> a[2];
            #pragma unroll
            for (int mi = 0; mi < 2; mi++)
                wmma::load_matrix_sync(a[mi], sA + (wm * 32 + mi * 16) * LDA + kk, LDA);
            #pragma unroll
            for (int ni = 0; ni < 2; ni++) {
                wmma::fragment<wmma::matrix_b, 16, 16, 16, __half, wmma::row_major> b;
                wmma::load_matrix_sync(b, sB + kk * LDB + wn * 32 + ni * 16, LDB);
                #pragma unroll
                for (int mi = 0; mi < 2; mi++)
                    wmma::mma_sync(acc[mi][ni], a[mi], b, acc[mi][ni]);
            }
        }
        __syncthreads();
    }

    #pragma unroll
    for (int mi = 0; mi < 2; mi++)
        #pragma unroll
        for (int ni = 0; ni < 2; ni++)
            wmma::store_matrix_sync(
                stagef + (wm * 32 + mi * 16) * LDS_ + wn * 32 + ni * 16,
                acc[mi][ni], LDS_, wmma::mem_row_major);
    __syncthreads();

    #pragma unroll 4
    for (int i = 0; i < (BM * BN) / (256 * 2); i++) {
        const int flat = i * 256 + tid;
        const int r = flat >> 6;
        const int c2 = flat & 63;
        const int n = nBase + c2 * 2;
        const float v0 = stagef[r * LDS_ + c2 * 2 + 0] + __ldg(&bias[n + 0]);
        const float v1 = stagef[r * LDS_ + c2 * 2 + 1] + __ldg(&bias[n + 1]);
        const int m = blockIdx.y * BM + r;
        *(float2*)&C[(size_t)m * N + n] = make_float2(v0, v1);
    }
}

// ---------------------------------------------------------------------------
// Routed attention v7: MIO-minimized two-phase.
// - Unshifted softmax (validated numerically in R15): after the 3-xor reduce
//   every lane of an 8-lane group holds the score, so each lane computes
//   w = exp(s/8) locally and KEEPS it in a register array -> the AV phase
//   needs no weight/select shuffles at all.
// - Routes for both queries packed into one shfl (16-bit ids, exact).
// - Two 8-route half-passes keep the w arrays at 16 registers.
// Shfls/query-pair: ~424 -> ~164; all arithmetic fp32 (no precision change).
// ---------------------------------------------------------------------------
__global__ __launch_bounds__(256) void attn_k(const int* __restrict__ routes)
{
    const unsigned FULL = 0xffffffffu;
    const int lane = threadIdx.x & 31;
    const int warp = threadIdx.x >> 5;
    const int chunks = SS / 32;
    const int bh = blockIdx.x / chunks;
    const int sc = blockIdx.x % chunks;
    const int b = bh >> 3, h = bh & 7;
    const int sub = lane & 7;
    const int grp = lane >> 3;

    const float*  Qb = g_q + (size_t)bh * SS * HDIM;
    const __half* Kb = gk + (size_t)bh * SS * HDIM;
    const __half* Vb = gv + (size_t)bh * SS * HDIM;

    #pragma unroll 1
    for (int qp = 0; qp < 2; qp++) {
        const int s0 = sc * 32 + warp * 4 + qp * 2;
        const int s1 = s0 + 1;

        const float4* qp0 = (const float4*)(Qb + (size_t)s0 * HDIM + sub * 8);
        const float4 q0a = qp0[0], q0b = qp0[1];
        const float4* qp1 = (const float4*)(Qb + (size_t)s1 * HDIM + sub * 8);
        const float4 q1a = qp1[0], q1b = qp1[1];

        // Both queries' route ids packed 16+16 bits (ids < 2048)
        const unsigned rp_lo = (unsigned)routes[s0 * KROUTE + lane]
                             | ((unsigned)routes[s1 * KROUTE + lane] << 16);
        const unsigned rp_hi = (unsigned)routes[s0 * KROUTE + 32 + lane]
                             | ((unsigned)routes[s1 * KROUTE + 32 + lane] << 16);

        float l0 = 0.f, l1 = 0.f;
        float4 a0a = make_float4(0.f, 0.f, 0.f, 0.f);
        float4 a0b = make_float4(0.f, 0.f, 0.f, 0.f);
        float4 a1a = make_float4(0.f, 0.f, 0.f, 0.f);
        float4 a1b = make_float4(0.f, 0.f, 0.f, 0.f);

        #pragma unroll 1
        for (int half = 0; half < 2; half++) {
            const unsigned rp = half ? rp_hi : rp_lo;
            float w0arr[8], w1arr[8];

            // ---- score sub-loop: 1 packed route shfl + 6 xor shfls / iter
            #pragma unroll
            for (int tt = 0; tt < 8; tt++) {
                const int kk31 = (((half * 8 + tt) * 4 + grp) & 31);
                const unsigned rr = __shfl_sync(FULL, rp, kk31);
                const int r0 = rr & 0xffff;
                const int r1 = rr >> 16;
                const uint4 kr0 = *(const uint4*)(Kb + (size_t)r0 * HDIM + sub * 8);
                const uint4 kr1 = *(const uint4*)(Kb + (size_t)r1 * HDIM + sub * 8);
                const __half2* kh0 = (const __half2*)&kr0;
                const __half2* kh1 = (const __half2*)&kr1;
                const float2 ka0 = __half22float2(kh0[0]);
                const float2 kb0 = __half22float2(kh0[1]);
                const float2 kc0 = __half22float2(kh0[2]);
                const float2 kd0 = __half22float2(kh0[3]);
                const float2 ka1 = __half22float2(kh1[0]);
                const float2 kb1 = __half22float2(kh1[1]);
                const float2 kc1 = __half22float2(kh1[2]);
                const float2 kd1 = __half22float2(kh1[3]);

                float p0 = ka0.x * q0a.x;
                p0 = fmaf(ka0.y, q0a.y, p0);
                p0 = fmaf(kb0.x, q0a.z, p0);
                p0 = fmaf(kb0.y, q0a.w, p0);
                p0 = fmaf(kc0.x, q0b.x, p0);
                p0 = fmaf(kc0.y, q0b.y, p0);
                p0 = fmaf(kd0.x, q0b.z, p0);
                p0 = fmaf(kd0.y, q0b.w, p0);
                float p1 = ka1.x * q1a.x;
                p1 = fmaf(ka1.y, q1a.y, p1);
                p1 = fmaf(kb1.x, q1a.z, p1);
                p1 = fmaf(kb1.y, q1a.w, p1);
                p1 = fmaf(kc1.x, q1b.x, p1);
                p1 = fmaf(kc1.y, q1b.y, p1);
                p1 = fmaf(kd1.x, q1b.z, p1);
                p1 = fmaf(kd1.y, q1b.w, p1);

                p0 += __shfl_xor_sync(FULL, p0, 1);
                p1 += __shfl_xor_sync(FULL, p1, 1);
                p0 += __shfl_xor_sync(FULL, p0, 2);
                p1 += __shfl_xor_sync(FULL, p1, 2);
                p0 += __shfl_xor_sync(FULL, p0, 4);
                p1 += __shfl_xor_sync(FULL, p1, 4);

                const float w0 = __expf(p0 * 0.125f);
                const float w1 = __expf(p1 * 0.125f);
                w0arr[tt] = w0;
                w1arr[tt] = w1;
                l0 += w0;
                l1 += w1;
            }

            // ---- AV sub-loop: 1 packed route shfl / iter, weights from regs
            #pragma unroll
            for (int tt = 0; tt < 8; tt++) {
                const int kk31 = (((half * 8 + tt) * 4 + grp) & 31);
                const unsigned rr = __shfl_sync(FULL, rp, kk31);
                const int r0 = rr & 0xffff;
                const int r1 = rr >> 16;
                const uint4 vr0 = *(const uint4*)(Vb + (size_t)r0 * HDIM + sub * 8);
                const uint4 vr1 = *(const uint4*)(Vb + (size_t)r1 * HDIM + sub * 8);
                const float w0 = w0arr[tt];
                const float w1 = w1arr[tt];
                const __half2* vh0 = (const __half2*)&vr0;
                const __half2* vh1 = (const __half2*)&vr1;
                const float2 va0 = __half22float2(vh0[0]);
                const float2 vb0 = __half22float2(vh0[1]);
                const float2 vc0 = __half22float2(vh0[2]);
                const float2 vd0 = __half22float2(vh0[3]);
                const float2 va1 = __half22float2(vh1[0]);
                const float2 vb1 = __half22float2(vh1[1]);
                const float2 vc1 = __half22float2(vh1[2]);
                const float2 vd1 = __half22float2(vh1[3]);
                a0a.x = fmaf(w0, va0.x, a0a.x);
                a0a.y = fmaf(w0, va0.y, a0a.y);
                a0a.z = fmaf(w0, vb0.x, a0a.z);
                a0a.w = fmaf(w0, vb0.y, a0a.w);
                a0b.x = fmaf(w0, vc0.x, a0b.x);
                a0b.y = fmaf(w0, vc0.y, a0b.y);
                a0b.z = fmaf(w0, vd0.x, a0b.z);
                a0b.w = fmaf(w0, vd0.y, a0b.w);
                a1a.x = fmaf(w1, va1.x, a1a.x);
                a1a.y = fmaf(w1, va1.y, a1a.y);
                a1a.z = fmaf(w1, vb1.x, a1a.z);
                a1a.w = fmaf(w1, vb1.y, a1a.w);
                a1b.x = fmaf(w1, vc1.x, a1b.x);
                a1b.y = fmaf(w1, vc1.y, a1b.y);
                a1b.z = fmaf(w1, vd1.x, a1b.z);
                a1b.w = fmaf(w1, vd1.y, a1b.w);
            }
        }

        // merge across the 4 groups (each group's lanes hold identical l)
        #pragma unroll
        for (int o = 8; o <= 16; o <<= 1) {
            l0 += __shfl_xor_sync(FULL, l0, o);
            l1 += __shfl_xor_sync(FULL, l1, o);
            a0a.x += __shfl_xor_sync(FULL, a0a.x, o);
            a0a.y += __shfl_xor_sync(FULL, a0a.y, o);
            a0a.z += __shfl_xor_sync(FULL, a0a.z, o);
            a0a.w += __shfl_xor_sync(FULL, a0a.w, o);
            a0b.x += __shfl_xor_sync(FULL, a0b.x, o);
            a0b.y += __shfl_xor_sync(FULL, a0b.y, o);
            a0b.z += __shfl_xor_sync(FULL, a0b.z, o);
            a0b.w += __shfl_xor_sync(FULL, a0b.w, o);
            a1a.x += __shfl_xor_sync(FULL, a1a.x, o);
            a1a.y += __shfl_xor_sync(FULL, a1a.y, o);
            a1a.z += __shfl_xor_sync(FULL, a1a.z, o);
            a1a.w += __shfl_xor_sync(FULL, a1a.w, o);
            a1b.x += __shfl_xor_sync(FULL, a1b.x, o);
            a1b.y += __shfl_xor_sync(FULL, a1b.y, o);
            a1b.z += __shfl_xor_sync(FULL, a1b.z, o);
            a1b.w += __shfl_xor_sync(FULL, a1b.w, o);
        }

        if (lane < 8) {
            const float inv0 = __fdividef(1.f, l0);
            const float inv1 = __fdividef(1.f, l1);
            #pragma unroll
            for (int qq = 0; qq < 2; qq++) {
                const int s = s0 + qq;
                const float inv = qq ? inv1 : inv0;
                const float4 xa = qq ? a1a : a0a;
                const float4 xb = qq ? a1b : a0b;
                const size_t off = ((size_t)(b * SS + s)) * DD + h * HDIM + sub * 8;
                __half2 hp[4];
                hp[0] = __floats2half2_rn(xa.x * inv, xa.y * inv);
                hp[1] = __floats2half2_rn(xa.z * inv, xa.w * inv);
                hp[2] = __floats2half2_rn(xb.x * inv, xb.y * inv);
                hp[3] = __floats2half2_rn(xb.z * inv, xb.w * inv);
                *(uint4*)&gat[off] = *(uint4*)hp;
            }
        }
    }
}

// ---------------------------------------------------------------------------
extern "C" void kernel_launch(void* const* d_in, const int* in_sizes, int n_in,
                              void* d_out, int out_size)
{
    const float* x      = (const float*)d_in[0];
    const float* Wqkv   = (const float*)d_in[1];
    const float* bqkv   = (const float*)d_in[2];
    const float* Wout   = (const float*)d_in[3];
    const float* bout   = (const float*)d_in[4];
    const int*   routes = (const int*)d_in[5];
    float* out = (float*)d_out;

    __half *ath, *xh, *w1h, *w2h;
    cudaGetSymbolAddress((void**)&ath, gat);
    cudaGetSymbolAddress((void**)&xh,  gx);
    cudaGetSymbolAddress((void**)&w1h, gw1);
    cudaGetSymbolAddress((void**)&w2h, gw2);

    constexpr int SMEM_QKV = 2 * (128 * 40 + 32 * 136) * 2;   // 37,888
    constexpr int SMEM_OUT = 64 * 132 * 4;                    // 33,792
    cudaFuncSetAttribute(gemm_qkv, cudaFuncAttributeMaxDynamicSharedMemorySize, SMEM_QKV);
    cudaFuncSetAttribute(gemm_out, cudaFuncAttributeMaxDynamicSharedMemorySize, SMEM_OUT);

    // 1) fused fp32 -> fp16 conversions (one launch)
    {
        constexpr int TOT = N4_X + N4_W1 + N4_W2;
        cvt_all<<<(TOT + 255) / 256, 256>>>(
            (const float4*)x, (const float4*)Wqkv, (const float4*)Wout);
    }

    // 2) QKV GEMM + head-scatter epilogue (q fp32, k/v fp16)
    gemm_qkv<<<dim3(3 * DD / 128, (BB * SS) / 128), 256, SMEM_QKV>>>(
        xh, w1h, bqkv, BB * SS, 3 * DD, DD);

    // 3) routed attention (MIO-minimized two-phase)
    attn_k<<<BB * HH * (SS / 32), 256>>>(routes);

    // 4) out projection (64x128 tiles, grid 4x64 = 256 CTAs)
    gemm_out<<<dim3(DD / 128, (BB * SS) / 64), 256, SMEM_OUT>>>(
        ath, w2h, bout, out, BB * SS, DD, DD);
}

// round 17
// speedup vs baseline: 1.1014x; 1.1014x over previous
#include <cuda_runtime.h>
#include <cuda_fp16.h>
#include <mma.h>
#include <cstdint>
#include <cstddef>

using namespace nvcuda;

#define BB 2
#define SS 2048
#define DD 512
#define HH 8
#define HDIM 64
#define KROUTE 64

// ---------------------------------------------------------------------------
// Scratch (device globals; no allocation allowed)
// ---------------------------------------------------------------------------
__device__ float g_q[BB * HH * SS * HDIM];
__device__ __align__(16) __half gk[BB * HH * SS * HDIM];
__device__ __align__(16) __half gv[BB * HH * SS * HDIM];

__device__ __align__(16) __half gx[BB * SS * DD];
__device__ __align__(16) __half gw1[DD * 3 * DD];
__device__ __align__(16) __half gw2[DD * DD];
__device__ __align__(16) __half gat[BB * SS * DD];

// ---------------------------------------------------------------------------
__device__ __forceinline__ void cp16(void* d, const void* s)
{
    unsigned ds = (unsigned)__cvta_generic_to_shared(d);
    asm volatile("cp.async.cg.shared.global [%0], [%1], 16;" :: "r"(ds), "l"(s));
}

// ---------------------------------------------------------------------------
// Fused fp32 -> fp16 conversion for x, Wqkv, Wout (single launch)
// ---------------------------------------------------------------------------
#define N4_X  ((BB * SS * DD) / 4)
#define N4_W1 ((DD * 3 * DD) / 4)
#define N4_W2 ((DD * DD) / 4)

__global__ __launch_bounds__(256) void cvt_all(
    const float4* __restrict__ x, const float4* __restrict__ w1,
    const float4* __restrict__ w2)
{
    int i = blockIdx.x * 256 + threadIdx.x;
    const float4* src;
    __half2* dst;
    if (i < N4_X) {
        src = x + i;
        dst = (__half2*)gx + 2 * i;
    } else if (i < N4_X + N4_W1) {
        const int j = i - N4_X;
        src = w1 + j;
        dst = (__half2*)gw1 + 2 * j;
    } else if (i < N4_X + N4_W1 + N4_W2) {
        const int j = i - N4_X - N4_W1;
        src = w2 + j;
        dst = (__half2*)gw2 + 2 * j;
    } else {
        return;
    }
    const float4 v = *src;
    dst[0] = __floats2half2_rn(v.x, v.y);
    dst[1] = __floats2half2_rn(v.z, v.w);
}

// ---------------------------------------------------------------------------
// Tensor-core GEMM (QKV), fp16 x fp16 -> fp32. 128x128x32 tile, 2-stage
// cp.async, 2 CTAs/SM. 8 warps: 4(m) x 2(n).
// Scatter epilogue: q->fp32, k/v->fp16 (head reshuffle), half2/float2 stores.
// ---------------------------------------------------------------------------
__global__ __launch_bounds__(256, 2) void gemm_qkv(
    const __half* __restrict__ A, const __half* __restrict__ B,
    const float* __restrict__ bias, int M, int N, int Kd)
{
    extern __shared__ __align__(16) char smem[];
    constexpr int BM = 128, BN = 128, BK = 32;
    constexpr int LDA = BK + 8;
    constexpr int LDB = BN + 8;
    constexpr int LDS_ = BN + 4;
    constexpr int A_SZ = BM * LDA;
    constexpr int B_SZ = BK * LDB;
    constexpr int STG = A_SZ + B_SZ;

    __half* base = (__half*)smem;
    float* stagef = (float*)smem;

    const int tid = threadIdx.x;
    const int wid = tid >> 5;
    const int wm = wid & 3;
    const int wn = wid >> 2;

    const size_t aBase = (size_t)blockIdx.y * BM * Kd;
    const int nBase = blockIdx.x * BN;
    const int nK = Kd / BK;

    wmma::fragment<wmma::accumulator, 16, 16, 16, float> acc[2][4];
    #pragma unroll
    for (int mi = 0; mi < 2; mi++)
        #pragma unroll
        for (int ni = 0; ni < 4; ni++) wmma::fill_fragment(acc[mi][ni], 0.0f);

    auto prefetch = [&](int ks, int st) {
        const int k0 = ks * BK;
        __half* sA = base + st * STG;
        __half* sB = sA + A_SZ;
        #pragma unroll
        for (int i = 0; i < 2; i++) {
            const int c = tid + 256 * i;
            const int rA = c >> 2, cA = (c & 3) * 8;
            cp16(&sA[rA * LDA + cA], A + aBase + (size_t)rA * Kd + k0 + cA);
            const int rB = c >> 4, cB = (c & 15) * 8;
            cp16(&sB[rB * LDB + cB], B + (size_t)(k0 + rB) * N + nBase + cB);
        }
        asm volatile("cp.async.commit_group;");
    };

    prefetch(0, 0);

    for (int ks = 0; ks < nK; ks++) {
        if (ks + 1 < nK) {
            prefetch(ks + 1, (ks + 1) & 1);
            asm volatile("cp.async.wait_group 1;");
        } else {
            asm volatile("cp.async.wait_group 0;");
        }
        __syncthreads();

        const int st = ks & 1;
        const __half* sA = base + st * STG;
        const __half* sB = sA + A_SZ;

        #pragma unroll
        for (int kk = 0; kk < BK; kk += 16) {
            wmma::fragment<wmma::matrix_a, 16, 16, 16, __half, wmma::row_major> a[2];
            #pragma unroll
            for (int mi = 0; mi < 2; mi++)
                wmma::load_matrix_sync(a[mi], sA + (wm * 32 + mi * 16) * LDA + kk, LDA);
            #pragma unroll
            for (int ni = 0; ni < 4; ni++) {
                wmma::fragment<wmma::matrix_b, 16, 16, 16, __half, wmma::row_major> b;
                wmma::load_matrix_sync(b, sB + kk * LDB + wn * 64 + ni * 16, LDB);
                #pragma unroll
                for (int mi = 0; mi < 2; mi++)
                    wmma::mma_sync(acc[mi][ni], a[mi], b, acc[mi][ni]);
            }
        }
        __syncthreads();
    }

    #pragma unroll
    for (int half = 0; half < 2; half++) {
        if ((wm >> 1) == half) {
            #pragma unroll
            for (int mi = 0; mi < 2; mi++)
                #pragma unroll
                for (int ni = 0; ni < 4; ni++)
                    wmma::store_matrix_sync(
                        stagef + ((wm & 1) * 32 + mi * 16) * LDS_ + wn * 64 + ni * 16,
                        acc[mi][ni], LDS_, wmma::mem_row_major);
        }
        __syncthreads();
        #pragma unroll 4
        for (int i = 0; i < (64 * BN) / (256 * 2); i++) {
            const int flat = i * 256 + tid;
            const int r = flat >> 6;
            const int c2 = flat & 63;
            const int n = nBase + c2 * 2;
            const float v0 = stagef[r * LDS_ + c2 * 2 + 0] + __ldg(&bias[n + 0]);
            const float v1 = stagef[r * LDS_ + c2 * 2 + 1] + __ldg(&bias[n + 1]);
            const int m = blockIdx.y * BM + half * 64 + r;
            const int b = m >> 11;
            const int s = m & 2047;
            const int c3 = n >> 9;
            const int h = (n >> 6) & 7;
            const int d = n & 63;
            const size_t off = (((size_t)b * HH + h) * SS + s) * HDIM + d;
            if (c3 == 0)      *(float2*)&g_q[off] = make_float2(v0, v1);
            else if (c3 == 1) *(__half2*)&gk[off] = __floats2half2_rn(v0, v1);
            else              *(__half2*)&gv[off] = __floats2half2_rn(v0, v1);
        }
        __syncthreads();
    }
}

// ---------------------------------------------------------------------------
// Out-projection GEMM: 64x128x32 tile (grid 4x64 = 256 CTAs), 2-stage
// cp.async, 3 CTAs/SM. 8 warps: 2(m) x 4(n), 32x32 warp tile.
// ---------------------------------------------------------------------------
__global__ __launch_bounds__(256, 3) void gemm_out(
    const __half* __restrict__ A, const __half* __restrict__ B,
    const float* __restrict__ bias, float* __restrict__ C,
    int M, int N, int Kd)
{
    extern __shared__ __align__(16) char smem[];
    constexpr int BM = 64, BN = 128, BK = 32;
    constexpr int LDA = BK + 8;    // 40
    constexpr int LDB = BN + 8;    // 136
    constexpr int LDS_ = BN + 4;   // 132
    constexpr int A_SZ = BM * LDA; // 2560
    constexpr int B_SZ = BK * LDB; // 4352
    constexpr int STG = A_SZ + B_SZ;

    __half* base = (__half*)smem;
    float* stagef = (float*)smem;

    const int tid = threadIdx.x;
    const int wid = tid >> 5;
    const int wm = wid & 1;
    const int wn = wid >> 1;

    const size_t aBase = (size_t)blockIdx.y * BM * Kd;
    const int nBase = blockIdx.x * BN;
    const int nK = Kd / BK;

    wmma::fragment<wmma::accumulator, 16, 16, 16, float> acc[2][2];
    #pragma unroll
    for (int mi = 0; mi < 2; mi++)
        #pragma unroll
        for (int ni = 0; ni < 2; ni++) wmma::fill_fragment(acc[mi][ni], 0.0f);

    auto prefetch = [&](int ks, int st) {
        const int k0 = ks * BK;
        __half* sA = base + st * STG;
        __half* sB = sA + A_SZ;
        {
            const int rA = tid >> 2, cA = (tid & 3) * 8;
            cp16(&sA[rA * LDA + cA], A + aBase + (size_t)rA * Kd + k0 + cA);
        }
        #pragma unroll
        for (int i = 0; i < 2; i++) {
            const int c = tid + 256 * i;
            const int rB = c >> 4, cB = (c & 15) * 8;
            cp16(&sB[rB * LDB + cB], B + (size_t)(k0 + rB) * N + nBase + cB);
        }
        asm volatile("cp.async.commit_group;");
    };

    prefetch(0, 0);

    for (int ks = 0; ks < nK; ks++) {
        if (ks + 1 < nK) {
            prefetch(ks + 1, (ks + 1) & 1);
            asm volatile("cp.async.wait_group 1;");
        } else {
            asm volatile("cp.async.wait_group 0;");
        }
        __syncthreads();

        const int st = ks & 1;
        const __half* sA = base + st * STG;
        const __half* sB = sA + A_SZ;

        #pragma unroll
        for (int kk = 0; kk < BK; kk += 16) {
            wmma::fragment<wmma::matrix_a, 16, 16, 16, __half, wmma::row_major> a[2];
            #pragma unroll
            for (int mi = 0; mi < 2; mi++)
                wmma::load_matrix_sync(a[mi], sA + (wm * 32 + mi * 16) * LDA + kk, LDA);
            #pragma unroll
            for (int ni = 0; ni < 2; ni++) {
                wmma::fragment<wmma::matrix_b, 16, 16, 16, __half, wmma::row_major> b;
                wmma::load_matrix_sync(b, sB + kk * LDB + wn * 32 + ni * 16, LDB);
                #pragma unroll
                for (int mi = 0; mi < 2; mi++)
                    wmma::mma_sync(acc[mi][ni], a[mi], b, acc[mi][ni]);
            }
        }
        __syncthreads();
    }

    #pragma unroll
    for (int mi = 0; mi < 2; mi++)
        #pragma unroll
        for (int ni = 0; ni < 2; ni++)
            wmma::store_matrix_sync(
                stagef + (wm * 32 + mi * 16) * LDS_ + wn * 32 + ni * 16,
                acc[mi][ni], LDS_, wmma::mem_row_major);
    __syncthreads();

    #pragma unroll 4
    for (int i = 0; i < (BM * BN) / (256 * 2); i++) {
        const int flat = i * 256 + tid;
        const int r = flat >> 6;
        const int c2 = flat & 63;
        const int n = nBase + c2 * 2;
        const float v0 = stagef[r * LDS_ + c2 * 2 + 0] + __ldg(&bias[n + 0]);
        const float v1 = stagef[r * LDS_ + c2 * 2 + 1] + __ldg(&bias[n + 1]);
        const int m = blockIdx.y * BM + r;
        *(float2*)&C[(size_t)m * N + n] = make_float2(v0, v1);
    }
}

// ---------------------------------------------------------------------------
// Routed attention: round-12 structure with two strictly-subtractive edits:
//  (a) unshifted softmax (validated exact enough): no max-reduce butterfly;
//  (b) both queries' route ids packed into one shuffle (exact, ids < 2048).
// Everything else (loop shape, selects, weight broadcasts) identical to the
// best-measured round-12 kernel.
// ---------------------------------------------------------------------------
__global__ __launch_bounds__(256) void attn_k(const int* __restrict__ routes)
{
    const unsigned FULL = 0xffffffffu;
    const int lane = threadIdx.x & 31;
    const int warp = threadIdx.x >> 5;
    const int chunks = SS / 32;
    const int bh = blockIdx.x / chunks;
    const int sc = blockIdx.x % chunks;
    const int b = bh >> 3, h = bh & 7;
    const int sub = lane & 7;
    const int grp = lane >> 3;

    const float*  Qb = g_q + (size_t)bh * SS * HDIM;
    const __half* Kb = gk + (size_t)bh * SS * HDIM;
    const __half* Vb = gv + (size_t)bh * SS * HDIM;

    #pragma unroll 1
    for (int qp = 0; qp < 2; qp++) {
        const int s0 = sc * 32 + warp * 4 + qp * 2;
        const int s1 = s0 + 1;

        const float4* qp0 = (const float4*)(Qb + (size_t)s0 * HDIM + sub * 8);
        const float4 q0a = qp0[0], q0b = qp0[1];
        const float4* qp1 = (const float4*)(Qb + (size_t)s1 * HDIM + sub * 8);
        const float4 q1a = qp1[0], q1b = qp1[1];

        // route ids for both queries packed 16+16 bits (exact, ids < 2048)
        const unsigned rp_lo = (unsigned)routes[s0 * KROUTE + lane]
                             | ((unsigned)routes[s1 * KROUTE + lane] << 16);
        const unsigned rp_hi = (unsigned)routes[s0 * KROUTE + 32 + lane]
                             | ((unsigned)routes[s1 * KROUTE + 32 + lane] << 16);

        float slo0 = 0.f, shi0 = 0.f, slo1 = 0.f, shi1 = 0.f;
        #pragma unroll
        for (int t = 0; t < 16; t++) {
            const int kk31 = (t * 4 + grp) & 31;
            const unsigned rr = __shfl_sync(FULL, (t < 8) ? rp_lo : rp_hi, kk31);
            const int r0 = rr & 0xffff;
            const int r1 = rr >> 16;
            const uint4 kr0 = *(const uint4*)(Kb + (size_t)r0 * HDIM + sub * 8);
            const uint4 kr1 = *(const uint4*)(Kb + (size_t)r1 * HDIM + sub * 8);
            const __half2* kh0 = (const __half2*)&kr0;
            const __half2* kh1 = (const __half2*)&kr1;
            const float2 ka0 = __half22float2(kh0[0]);
            const float2 kb0 = __half22float2(kh0[1]);
            const float2 kc0 = __half22float2(kh0[2]);
            const float2 kd0 = __half22float2(kh0[3]);
            const float2 ka1 = __half22float2(kh1[0]);
            const float2 kb1 = __half22float2(kh1[1]);
            const float2 kc1 = __half22float2(kh1[2]);
            const float2 kd1 = __half22float2(kh1[3]);

            float p0 = ka0.x * q0a.x;
            p0 = fmaf(ka0.y, q0a.y, p0);
            p0 = fmaf(kb0.x, q0a.z, p0);
            p0 = fmaf(kb0.y, q0a.w, p0);
            p0 = fmaf(kc0.x, q0b.x, p0);
            p0 = fmaf(kc0.y, q0b.y, p0);
            p0 = fmaf(kd0.x, q0b.z, p0);
            p0 = fmaf(kd0.y, q0b.w, p0);
            float p1 = ka1.x * q1a.x;
            p1 = fmaf(ka1.y, q1a.y, p1);
            p1 = fmaf(kb1.x, q1a.z, p1);
            p1 = fmaf(kb1.y, q1a.w, p1);
            p1 = fmaf(kc1.x, q1b.x, p1);
            p1 = fmaf(kc1.y, q1b.y, p1);
            p1 = fmaf(kd1.x, q1b.z, p1);
            p1 = fmaf(kd1.y, q1b.w, p1);

            p0 += __shfl_xor_sync(FULL, p0, 1);
            p1 += __shfl_xor_sync(FULL, p1, 1);
            p0 += __shfl_xor_sync(FULL, p0, 2);
            p1 += __shfl_xor_sync(FULL, p1, 2);
            p0 += __shfl_xor_sync(FULL, p0, 4);
            p1 += __shfl_xor_sync(FULL, p1, 4);
            const float v0 = __shfl_sync(FULL, p0, (lane & 3) * 8);
            const float v1 = __shfl_sync(FULL, p1, (lane & 3) * 8);
            if ((lane >> 2) == t)     { slo0 = v0; slo1 = v1; }
            if ((lane >> 2) + 8 == t) { shi0 = v0; shi1 = v1; }
        }

        // unshifted softmax (scores |s| <~ 12: exp is safe in fp32)
        const float elo0 = __expf(slo0 * 0.125f), ehi0 = __expf(shi0 * 0.125f);
        const float elo1 = __expf(slo1 * 0.125f), ehi1 = __expf(shi1 * 0.125f);
        float sum0 = elo0 + ehi0;
        float sum1 = elo1 + ehi1;
        #pragma unroll
        for (int o = 16; o; o >>= 1) {
            sum0 += __shfl_xor_sync(FULL, sum0, o);
            sum1 += __shfl_xor_sync(FULL, sum1, o);
        }
        const float inv0 = __fdividef(1.f, sum0);
        const float inv1 = __fdividef(1.f, sum1);
        const float wlo0 = elo0 * inv0, whi0 = ehi0 * inv0;
        const float wlo1 = elo1 * inv1, whi1 = ehi1 * inv1;

        float4 a0a = make_float4(0.f, 0.f, 0.f, 0.f);
        float4 a0b = make_float4(0.f, 0.f, 0.f, 0.f);
        float4 a1a = make_float4(0.f, 0.f, 0.f, 0.f);
        float4 a1b = make_float4(0.f, 0.f, 0.f, 0.f);
        #pragma unroll
        for (int t = 0; t < 16; t++) {
            const int kk31 = (t * 4 + grp) & 31;
            const unsigned rr = __shfl_sync(FULL, (t < 8) ? rp_lo : rp_hi, kk31);
            const int r0 = rr & 0xffff;
            const int r1 = rr >> 16;
            const float w0 = __shfl_sync(FULL, (t < 8) ? wlo0 : whi0, kk31);
            const float w1 = __shfl_sync(FULL, (t < 8) ? wlo1 : whi1, kk31);
            const uint4 vr0 = *(const uint4*)(Vb + (size_t)r0 * HDIM + sub * 8);
            const uint4 vr1 = *(const uint4*)(Vb + (size_t)r1 * HDIM + sub * 8);
            const __half2* vh0 = (const __half2*)&vr0;
            const __half2* vh1 = (const __half2*)&vr1;
            const float2 va0 = __half22float2(vh0[0]);
            const float2 vb0 = __half22float2(vh0[1]);
            const float2 vc0 = __half22float2(vh0[2]);
            const float2 vd0 = __half22float2(vh0[3]);
            const float2 va1 = __half22float2(vh1[0]);
            const float2 vb1 = __half22float2(vh1[1]);
            const float2 vc1 = __half22float2(vh1[2]);
            const float2 vd1 = __half22float2(vh1[3]);
            a0a.x = fmaf(w0, va0.x, a0a.x);
            a0a.y = fmaf(w0, va0.y, a0a.y);
            a0a.z = fmaf(w0, vb0.x, a0a.z);
            a0a.w = fmaf(w0, vb0.y, a0a.w);
            a0b.x = fmaf(w0, vc0.x, a0b.x);
            a0b.y = fmaf(w0, vc0.y, a0b.y);
            a0b.z = fmaf(w0, vd0.x, a0b.z);
            a0b.w = fmaf(w0, vd0.y, a0b.w);
            a1a.x = fmaf(w1, va1.x, a1a.x);
            a1a.y = fmaf(w1, va1.y, a1a.y);
            a1a.z = fmaf(w1, vb1.x, a1a.z);
            a1a.w = fmaf(w1, vb1.y, a1a.w);
            a1b.x = fmaf(w1, vc1.x, a1b.x);
            a1b.y = fmaf(w1, vc1.y, a1b.y);
            a1b.z = fmaf(w1, vd1.x, a1b.z);
            a1b.w = fmaf(w1, vd1.y, a1b.w);
        }
        #pragma unroll
        for (int o = 8; o <= 16; o <<= 1) {
            a0a.x += __shfl_xor_sync(FULL, a0a.x, o);
            a0a.y += __shfl_xor_sync(FULL, a0a.y, o);
            a0a.z += __shfl_xor_sync(FULL, a0a.z, o);
            a0a.w += __shfl_xor_sync(FULL, a0a.w, o);
            a0b.x += __shfl_xor_sync(FULL, a0b.x, o);
            a0b.y += __shfl_xor_sync(FULL, a0b.y, o);
            a0b.z += __shfl_xor_sync(FULL, a0b.z, o);
            a0b.w += __shfl_xor_sync(FULL, a0b.w, o);
            a1a.x += __shfl_xor_sync(FULL, a1a.x, o);
            a1a.y += __shfl_xor_sync(FULL, a1a.y, o);
            a1a.z += __shfl_xor_sync(FULL, a1a.z, o);
            a1a.w += __shfl_xor_sync(FULL, a1a.w, o);
            a1b.x += __shfl_xor_sync(FULL, a1b.x, o);
            a1b.y += __shfl_xor_sync(FULL, a1b.y, o);
            a1b.z += __shfl_xor_sync(FULL, a1b.z, o);
            a1b.w += __shfl_xor_sync(FULL, a1b.w, o);
        }

        if (lane < 8) {
            #pragma unroll
            for (int qq = 0; qq < 2; qq++) {
                const int s = s0 + qq;
                const float4 xa = qq ? a1a : a0a;
                const float4 xb = qq ? a1b : a0b;
                const size_t off = ((size_t)(b * SS + s)) * DD + h * HDIM + sub * 8;
                __half2 hp[4];
                hp[0] = __floats2half2_rn(xa.x, xa.y);
                hp[1] = __floats2half2_rn(xa.z, xa.w);
                hp[2] = __floats2half2_rn(xb.x, xb.y);
                hp[3] = __floats2half2_rn(xb.z, xb.w);
                *(uint4*)&gat[off] = *(uint4*)hp;
            }
        }
    }
}

// ---------------------------------------------------------------------------
extern "C" void kernel_launch(void* const* d_in, const int* in_sizes, int n_in,
                              void* d_out, int out_size)
{
    const float* x      = (const float*)d_in[0];
    const float* Wqkv   = (const float*)d_in[1];
    const float* bqkv   = (const float*)d_in[2];
    const float* Wout   = (const float*)d_in[3];
    const float* bout   = (const float*)d_in[4];
    const int*   routes = (const int*)d_in[5];
    float* out = (float*)d_out;

    __half *ath, *xh, *w1h, *w2h;
    cudaGetSymbolAddress((void**)&ath, gat);
    cudaGetSymbolAddress((void**)&xh,  gx);
    cudaGetSymbolAddress((void**)&w1h, gw1);
    cudaGetSymbolAddress((void**)&w2h, gw2);

    constexpr int SMEM_QKV = 2 * (128 * 40 + 32 * 136) * 2;   // 37,888
    constexpr int SMEM_OUT = 64 * 132 * 4;                    // 33,792
    cudaFuncSetAttribute(gemm_qkv, cudaFuncAttributeMaxDynamicSharedMemorySize, SMEM_QKV);
    cudaFuncSetAttribute(gemm_out, cudaFuncAttributeMaxDynamicSharedMemorySize, SMEM_OUT);

    // 1) fused fp32 -> fp16 conversions (one launch)
    {
        constexpr int TOT = N4_X + N4_W1 + N4_W2;
        cvt_all<<<(TOT + 255) / 256, 256>>>(
            (const float4*)x, (const float4*)Wqkv, (const float4*)Wout);
    }

    // 2) QKV GEMM + head-scatter epilogue (q fp32, k/v fp16)
    gemm_qkv<<<dim3(3 * DD / 128, (BB * SS) / 128), 256, SMEM_QKV>>>(
        xh, w1h, bqkv, BB * SS, 3 * DD, DD);

    // 3) routed attention (round-12 shape, minus max-butterfly, packed routes)
    attn_k<<<BB * HH * (SS / 32), 256>>>(routes);

    // 4) out projection (64x128 tiles, grid 4x64 = 256 CTAs)
    gemm_out<<<dim3(DD / 128, (BB * SS) / 64), 256, SMEM_OUT>>>(
        ath, w2h, bout, out, BB * SS, DD, DD);
}